// round 11
// baseline (speedup 1.0000x reference)
#include <cuda_runtime.h>
#include <cuda_fp16.h>
#include <cstdint>

// ---------------------------------------------------------------------------
// MiniMoE: grouped single-pass fp16 mma.sync GEMMs, fp32 accumulate.
//   out[t] = sum_k w[t,k] * relu( relu( x[t] @ W1[e]^T ) @ W2[e]^T )
// R10: 64x64 warp tiles (4 warps / 128 threads per CTA) to cut ldmatrix
// smem traffic 33% — smem crossbar was co-bottleneck with tensor pipe.
// ---------------------------------------------------------------------------

namespace {
constexpr int T_TOK = 8192;
constexpr int D_DIM = 1024;
constexpr int E_EXP = 8;
constexpr int A_TOT = T_TOK * 2;            // 16384 assignments (K=2)

constexpr int BM = 128, BN = 128;
constexpr int KC = 32;                      // elems per K chunk
constexpr int NCHUNK = D_DIM / KC;          // 32
constexpr int MAXROWS = A_TOT + E_EXP * BM; // 17408
constexpr int MTILES  = MAXROWS / BM;       // 136
constexpr int NTILES  = D_DIM / BN;         // 8

constexpr int TILE_B  = 128 * 40 * 2;       // 10240 B (80B-stride rows)
constexpr int OFF_A   = 0;
constexpr int OFF_B   = TILE_B;
constexpr int STAGE_B = 2 * TILE_B;         // 20480
constexpr int NSTAGE  = 4;
constexpr int SMEM_BYTES = NSTAGE * STAGE_B; // 81920 -> 2 CTAs/SM
}

// ---------------- scratch ---------------------------------------------------
__device__ int    g_cursor[E_EXP];
__device__ int    g_pad_off[E_EXP + 1];
__device__ int    g_row_token[MAXROWS];
__device__ int    g_assign_row[A_TOT];

__device__ __half g_Xh[(size_t)T_TOK * D_DIM];
__device__ __half g_W1h[(size_t)E_EXP * D_DIM * D_DIM];
__device__ __half g_W2h[(size_t)E_EXP * D_DIM * D_DIM];
__device__ __half g_Hh[(size_t)MAXROWS * D_DIM];
__device__ float  g_Y [(size_t)MAXROWS * D_DIM];

// ---------------- PTX helpers ----------------------------------------------
__device__ __forceinline__ uint32_t smem_u32(const void* p) {
    uint32_t a;
    asm("{ .reg .u64 t; cvta.to.shared.u64 t, %1; cvt.u32.u64 %0, t; }" : "=r"(a) : "l"(p));
    return a;
}
__device__ __forceinline__ void cp16(uint32_t dst, const void* src) {
    asm volatile("cp.async.cg.shared.global [%0], [%1], 16;" :: "r"(dst), "l"(src));
}
#define CP_COMMIT() asm volatile("cp.async.commit_group;" ::: "memory")
#define CP_WAIT1()  asm volatile("cp.async.wait_group 1;" ::: "memory")

__device__ __forceinline__ void ldsm4(uint32_t& r0, uint32_t& r1, uint32_t& r2, uint32_t& r3,
                                      uint32_t addr) {
    asm volatile("ldmatrix.sync.aligned.m8n8.x4.shared.b16 {%0,%1,%2,%3}, [%4];"
                 : "=r"(r0), "=r"(r1), "=r"(r2), "=r"(r3) : "r"(addr));
}
__device__ __forceinline__ void mma16816(float* c, const uint32_t* a, const uint32_t* b) {
    asm volatile("mma.sync.aligned.m16n8k16.row.col.f32.f16.f16.f32 "
                 "{%0,%1,%2,%3}, {%4,%5,%6,%7}, {%8,%9}, {%0,%1,%2,%3};"
                 : "+f"(c[0]), "+f"(c[1]), "+f"(c[2]), "+f"(c[3])
                 : "r"(a[0]), "r"(a[1]), "r"(a[2]), "r"(a[3]), "r"(b[0]), "r"(b[1]));
}

// ---------------- prep: hist + scan + fill (single block) -------------------
__global__ void k_prep(const int* __restrict__ idx) {
    __shared__ int cnt[E_EXP];
    const int t = threadIdx.x;
    if (t < E_EXP) cnt[t] = 0;
    __syncthreads();
    for (int i = t; i < A_TOT; i += blockDim.x) atomicAdd(&cnt[idx[i]], 1);
    __syncthreads();
    if (t == 0) {
        int off = 0;
        for (int e = 0; e < E_EXP; e++) {
            g_pad_off[e] = off;
            g_cursor[e] = 0;
            off += ((cnt[e] + BM - 1) / BM) * BM;
        }
        g_pad_off[E_EXP] = off;
    }
    for (int i = t; i < MAXROWS; i += blockDim.x) g_row_token[i] = 0;
}

__global__ void k_scatter(const int* __restrict__ idx) {
    int i = blockIdx.x * blockDim.x + threadIdx.x;
    if (i < A_TOT) {
        int e = idx[i];
        int pos = g_pad_off[e] + atomicAdd(&g_cursor[e], 1);
        g_row_token[pos] = i >> 1;
        g_assign_row[i] = pos;
    }
}

// ---------------- fp32 -> fp16 converts (X, W1, W2) -------------------------
// All three regions are exactly 2^21 float4s; region = blockIdx.x >> 13.
__global__ void k_cvt_all(const float4* __restrict__ x,
                          const float4* __restrict__ w1,
                          const float4* __restrict__ w2) {
    const int region = blockIdx.x >> 13;
    const int i = ((blockIdx.x & 8191) << 8) + threadIdx.x;
    const float4 v = (region == 0) ? x[i] : (region == 1) ? w1[i] : w2[i];
    __half* dst = (region == 0) ? g_Xh : (region == 1) ? g_W1h : g_W2h;
    reinterpret_cast<__half2*>(dst)[i * 2 + 0] = __floats2half2_rn(v.x, v.y);
    reinterpret_cast<__half2*>(dst)[i * 2 + 1] = __floats2half2_rn(v.z, v.w);
}

// ---------------------------------------------------------------------------
// Grouped GEMM: C = relu(A @ B[e]^T), fp16 operands, fp32 accumulate.
// 128 threads / 4 warps; each warp owns a 64x64 output tile.
// LAYER 1: A rows gathered via g_row_token; out -> Hh (fp16).
// LAYER 2: A = H rows (identity);           out -> Y (fp32).
// 4-stage cp.async ring, prefetch distance 2, one barrier per chunk.
// ---------------------------------------------------------------------------
template <int LAYER>
__global__ __launch_bounds__(128, 2)
void k_gemm(const __half* __restrict__ Ap, const __half* __restrict__ Bp) {
    extern __shared__ __align__(128) char sm[];

    const int m0 = blockIdx.x * BM;
    if (m0 >= g_pad_off[E_EXP]) return;

    int e = 0;
#pragma unroll
    for (int i = 1; i <= E_EXP; i++)
        if (m0 >= g_pad_off[i]) e = i;

    const __half* Bh = Bp + (size_t)e * D_DIM * D_DIM;
    const int n0 = blockIdx.y * BN;
    const int tid = threadIdx.x;
    const uint32_t smb = smem_u32(sm);

    // ---- loaders: thread covers rows rw+32i (i=0..3); 16B segment seg ----
    const int seg = tid & 3;
    const int rw  = tid >> 2;                 // 0..31
    uint32_t dst[4];
    const char *pA[4], *pB[4];
#pragma unroll
    for (int i = 0; i < 4; i++) {
        const int row = rw + 32 * i;
        dst[i] = (uint32_t)row * 80 + seg * 16;
        if (LAYER == 1) {
            const int tk = g_row_token[m0 + row];
            pA[i] = (const char*)(Ap + (size_t)tk * D_DIM) + seg * 16;
        } else {
            pA[i] = (const char*)(Ap + (size_t)(m0 + row) * D_DIM) + seg * 16;
        }
        pB[i] = (const char*)(Bh + (size_t)(n0 + row) * D_DIM) + seg * 16;
    }

    auto prefetch = [&](int c, int st) {
        const uint32_t b = smb + (uint32_t)st * STAGE_B;
        const size_t o = (size_t)c * 64;      // 32 halfs per chunk = 64 B
#pragma unroll
        for (int i = 0; i < 4; i++) {
            cp16(b + OFF_A + dst[i], pA[i] + o);
            cp16(b + OFF_B + dst[i], pB[i] + o);
        }
    };

    // ---- fragment addressing: warp (wm, wn) owns rows wm*64.., cols wn*64.. ----
    const int lane = tid & 31, wid = tid >> 5;
    const int wm = wid & 1;
    const int wn = wid >> 1;
    const uint32_t laneA = (uint32_t)(lane & 15) * 80 + (lane >> 4) * 16;
    const uint32_t laneB = (uint32_t)(((lane >> 4) & 1) * 8 + (lane & 7)) * 80
                         + ((lane >> 3) & 1) * 16;
    uint32_t aOff[4], bOff[4];
#pragma unroll
    for (int mt = 0; mt < 4; mt++) aOff[mt] = (uint32_t)(wm * 64 + mt * 16) * 80 + laneA;
#pragma unroll
    for (int tp = 0; tp < 4; tp++) bOff[tp] = (uint32_t)(wn * 64 + tp * 16) * 80 + laneB;

    float acc[32][4];
#pragma unroll
    for (int i = 0; i < 32; i++)
#pragma unroll
        for (int j = 0; j < 4; j++) acc[i][j] = 0.f;

    prefetch(0, 0); CP_COMMIT();
    prefetch(1, 1); CP_COMMIT();

    for (int c = 0; c < NCHUNK; c++) {
        CP_WAIT1();                           // own stage-c copies complete
        __syncthreads();                      // everyone's stage-c copies visible
        if (c + 2 < NCHUNK) prefetch(c + 2, (c + 2) & 3);
        CP_COMMIT();

        const uint32_t sb = smb + (uint32_t)(c & 3) * STAGE_B;
#pragma unroll
        for (int kk = 0; kk < 2; kk++) {
            const uint32_t ko = kk * 32;      // 16 halfs
            uint32_t ah[16], bh[16];
#pragma unroll
            for (int mt = 0; mt < 4; mt++)
                ldsm4(ah[4*mt], ah[4*mt+1], ah[4*mt+2], ah[4*mt+3],
                      sb + OFF_A + aOff[mt] + ko);
#pragma unroll
            for (int tp = 0; tp < 4; tp++)
                ldsm4(bh[4*tp], bh[4*tp+1], bh[4*tp+2], bh[4*tp+3],
                      sb + OFF_B + bOff[tp] + ko);
#pragma unroll
            for (int mt = 0; mt < 4; mt++)
#pragma unroll
                for (int nt = 0; nt < 8; nt++)
                    mma16816(acc[mt*8 + nt], &ah[mt*4], &bh[nt*2]);
        }
    }

    // ---- epilogue ----
#pragma unroll
    for (int mt = 0; mt < 4; mt++) {
#pragma unroll
        for (int nt = 0; nt < 8; nt++) {
            const float* a = acc[mt*8+nt];
            const int r  = m0 + wm * 64 + mt * 16 + (lane >> 2);
            const int cc = n0 + wn * 64 + nt * 8 + (lane & 3) * 2;
            if (LAYER == 1) {
                *reinterpret_cast<__half2*>(&g_Hh[(size_t)r * D_DIM + cc]) =
                    __floats2half2_rn(fmaxf(a[0], 0.f), fmaxf(a[1], 0.f));
                *reinterpret_cast<__half2*>(&g_Hh[(size_t)(r + 8) * D_DIM + cc]) =
                    __floats2half2_rn(fmaxf(a[2], 0.f), fmaxf(a[3], 0.f));
            } else {
                float2 o0 = make_float2(fmaxf(a[0], 0.f), fmaxf(a[1], 0.f));
                float2 o1 = make_float2(fmaxf(a[2], 0.f), fmaxf(a[3], 0.f));
                *reinterpret_cast<float2*>(&g_Y[(size_t)r * D_DIM + cc]) = o0;
                *reinterpret_cast<float2*>(&g_Y[(size_t)(r + 8) * D_DIM + cc]) = o1;
            }
        }
    }
}

// ---------------- deterministic combine ------------------------------------
__global__ void k_combine(const float* __restrict__ wts, float* __restrict__ out) {
    const int gid = blockIdx.x * blockDim.x + threadIdx.x;
    if (gid >= T_TOK * (D_DIM / 4)) return;
    const int t = gid / (D_DIM / 4);
    const int c = (gid % (D_DIM / 4)) * 4;

    const int   r0 = g_assign_row[2 * t];
    const int   r1 = g_assign_row[2 * t + 1];
    const float w0 = wts[2 * t];
    const float w1 = wts[2 * t + 1];

    const float4 y0 = *reinterpret_cast<const float4*>(&g_Y[(size_t)r0 * D_DIM + c]);
    const float4 y1 = *reinterpret_cast<const float4*>(&g_Y[(size_t)r1 * D_DIM + c]);
    float4 o;
    o.x = w0 * y0.x + w1 * y1.x;
    o.y = w0 * y0.y + w1 * y1.y;
    o.z = w0 * y0.z + w1 * y1.z;
    o.w = w0 * y0.w + w1 * y1.w;
    *reinterpret_cast<float4*>(out + (size_t)t * D_DIM + c) = o;
}

// ---------------------------------------------------------------------------
extern "C" void kernel_launch(void* const* d_in, const int* in_sizes, int n_in,
                              void* d_out, int out_size) {
    const float* x   = (const float*)d_in[0];
    const int*   idx = (const int*)  d_in[1];
    const float* wts = (const float*)d_in[2];
    const float* W1  = (const float*)d_in[3];
    const float* W2  = (const float*)d_in[4];
    float* out = (float*)d_out;

    cudaFuncSetAttribute(k_gemm<1>, cudaFuncAttributeMaxDynamicSharedMemorySize, SMEM_BYTES);
    cudaFuncSetAttribute(k_gemm<2>, cudaFuncAttributeMaxDynamicSharedMemorySize, SMEM_BYTES);

    __half *xh, *w1h, *w2h, *hh;
    cudaGetSymbolAddress((void**)&xh,  g_Xh);
    cudaGetSymbolAddress((void**)&w1h, g_W1h);
    cudaGetSymbolAddress((void**)&w2h, g_W2h);
    cudaGetSymbolAddress((void**)&hh,  g_Hh);

    k_prep<<<1, 1024>>>(idx);                                   // 1
    k_scatter<<<(A_TOT + 255) / 256, 256>>>(idx);               // 2
    k_cvt_all<<<3 * 8192, 256>>>((const float4*)x,              // 3
                                 (const float4*)W1, (const float4*)W2);

    dim3 ggrid(MTILES, NTILES);
    k_gemm<1><<<ggrid, 128, SMEM_BYTES>>>(xh, w1h);             // 4 (profiled slot)
    k_gemm<2><<<ggrid, 128, SMEM_BYTES>>>(hh, w2h);             // 5

    k_combine<<<(T_TOK * D_DIM / 4 + 255) / 256, 256>>>(wts, out); // 6
}